// round 3
// baseline (speedup 1.0000x reference)
#include <cuda_runtime.h>
#include <cuda_bf16.h>
#include <cuda_fp8.h>
#include <cstdint>

// ---------------------------------------------------------------------------
// MoE layer (T=16384, D=1024, E=8, top-2), mma.sync edition for sm_103 PTX:
//   bf16 hi*hi main GEMM  +  fp8(e4m3, k32) correction terms (Ah*Bl + Al*Bh).
//   C = Chh + Ccorr/256.  3-stage cp.async pipeline, 1 sync per K-iter.
// ---------------------------------------------------------------------------

namespace {
constexpr int TT = 16384;
constexpr int DD = 1024;
constexpr int NE = 8;
constexpr int NP = TT * 2;          // 32768
constexpr int MAXT = 264;

constexpr int BM = 128, BN = 128, BK = 32;
constexpr int KT = DD / BK;         // 32
constexpr int NSTAGE = 3;

constexpr int SAK = 40;             // A bf16 smem row stride (elems)
constexpr int SBN = 136;            // B bf16 smem row stride (elems)
constexpr int S8  = 48;             // fp8 smem row stride (bytes)

constexpr int OFF_AH  = 0;          // 128*40*2  = 10240
constexpr int OFF_BH  = 10240;      // 32*136*2  =  8704
constexpr int OFF_A8H = 18944;      // 128*48    =  6144
constexpr int OFF_A8L = 25088;
constexpr int OFF_B8H = 31232;
constexpr int OFF_B8L = 37376;
constexpr int STAGE   = 43520;
constexpr int SMEM_BYTES = NSTAGE * STAGE;   // 130560
} // namespace

// ------------------------- device scratch (static) -------------------------
__device__ int g_counts[NE];
__device__ int g_offsets[NE + 1];
__device__ int g_cursor[NE];
__device__ int g_pair_expert[NP];
__device__ float g_pair_w[NP];
__device__ int g_bucket_pair[NP];
__device__ int g_row_of_pair[NP];
__device__ int g_tile_e[MAXT];
__device__ int g_tile_row[MAXT];
__device__ int g_num_tiles;

__device__ __nv_bfloat16 g_Whi[3ull * NE * DD * DD];   // [sec][e][k][n] bf16 hi
__device__ uint8_t       g_W8h[3ull * NE * DD * DD];   // [sec][e][n][k] e4m3(hi)
__device__ uint8_t       g_W8l[3ull * NE * DD * DD];   // [sec][e][n][k] e4m3(lo*256)
__device__ __nv_bfloat16 g_Xh[(size_t)NP * DD];
__device__ uint8_t       g_X8h[(size_t)NP * DD];
__device__ uint8_t       g_X8l[(size_t)NP * DD];
__device__ float         g_t1[(size_t)NP * DD];        // gate, later down-out
__device__ float         g_t2[(size_t)NP * DD];        // up
__device__ __nv_bfloat16 g_A2h[(size_t)NP * DD];
__device__ uint8_t       g_A28h[(size_t)NP * DD];
__device__ uint8_t       g_A28l[(size_t)NP * DD];

// ------------------------------- helpers -----------------------------------
__device__ __forceinline__ uint32_t smem_u32(const void* p) {
    return (uint32_t)__cvta_generic_to_shared(p);
}
__device__ __forceinline__ void cp16(uint32_t s, const void* g, bool pred) {
    int sz = pred ? 16 : 0;
    asm volatile("cp.async.cg.shared.global [%0], [%1], 16, %2;\n"
                 :: "r"(s), "l"(g), "r"(sz));
}
__device__ __forceinline__ void ldsm4(uint32_t* r, uint32_t addr) {
    asm volatile("ldmatrix.sync.aligned.m8n8.x4.shared.b16 {%0,%1,%2,%3}, [%4];"
                 : "=r"(r[0]), "=r"(r[1]), "=r"(r[2]), "=r"(r[3]) : "r"(addr));
}
__device__ __forceinline__ void ldsm2(uint32_t* r, uint32_t addr) {
    asm volatile("ldmatrix.sync.aligned.m8n8.x2.shared.b16 {%0,%1}, [%2];"
                 : "=r"(r[0]), "=r"(r[1]) : "r"(addr));
}
__device__ __forceinline__ void ldsm2t(uint32_t* r, uint32_t addr) {
    asm volatile("ldmatrix.sync.aligned.m8n8.x2.trans.shared.b16 {%0,%1}, [%2];"
                 : "=r"(r[0]), "=r"(r[1]) : "r"(addr));
}
__device__ __forceinline__ void mma_bf16(float* c, const uint32_t* a, const uint32_t* b) {
    asm volatile(
        "mma.sync.aligned.m16n8k16.row.col.f32.bf16.bf16.f32 "
        "{%0,%1,%2,%3}, {%4,%5,%6,%7}, {%8,%9}, {%0,%1,%2,%3};\n"
        : "+f"(c[0]), "+f"(c[1]), "+f"(c[2]), "+f"(c[3])
        : "r"(a[0]), "r"(a[1]), "r"(a[2]), "r"(a[3]), "r"(b[0]), "r"(b[1]));
}
__device__ __forceinline__ void mma_fp8(float* c, const uint32_t* a, const uint32_t* b) {
    asm volatile(
        "mma.sync.aligned.m16n8k32.row.col.f32.e4m3.e4m3.f32 "
        "{%0,%1,%2,%3}, {%4,%5,%6,%7}, {%8,%9}, {%0,%1,%2,%3};\n"
        : "+f"(c[0]), "+f"(c[1]), "+f"(c[2]), "+f"(c[3])
        : "r"(a[0]), "r"(a[1]), "r"(a[2]), "r"(a[3]), "r"(b[0]), "r"(b[1]));
}
__device__ __forceinline__ uint8_t f2e4m3(float v) {
    return (uint8_t)__nv_cvt_float_to_fp8(v, __NV_SATFINITE, __NV_E4M3);
}

// ------------------------------- small kernels ------------------------------
__global__ void init_kernel() {
    int i = threadIdx.x;
    if (i < NE) g_counts[i] = 0;
}

__global__ void router_kernel(const float* __restrict__ x,
                              const float* __restrict__ rw,
                              const float* __restrict__ rb) {
    int warp = threadIdx.x >> 5;
    int lane = threadIdx.x & 31;
    int token = blockIdx.x * (blockDim.x >> 5) + warp;
    if (token >= TT) return;

    const float4* xr = (const float4*)(x + (size_t)token * DD);
    float acc[NE];
    #pragma unroll
    for (int e = 0; e < NE; e++) acc[e] = 0.f;
    for (int i = lane; i < DD / 4; i += 32) {
        float4 v = xr[i];
        const float* r0 = rw + i * 4 * NE;
        #pragma unroll
        for (int e = 0; e < NE; e++)
            acc[e] += v.x * r0[e] + v.y * r0[NE + e] + v.z * r0[2 * NE + e] + v.w * r0[3 * NE + e];
    }
    #pragma unroll
    for (int off = 16; off; off >>= 1)
        #pragma unroll
        for (int e = 0; e < NE; e++)
            acc[e] += __shfl_xor_sync(0xFFFFFFFFu, acc[e], off);

    if (lane == 0) {
        #pragma unroll
        for (int e = 0; e < NE; e++) acc[e] += rb[e];
        int i0 = 0;
        #pragma unroll
        for (int e = 1; e < NE; e++) if (acc[e] > acc[i0]) i0 = e;
        int i1 = (i0 == 0) ? 1 : 0;
        #pragma unroll
        for (int e = 0; e < NE; e++) if (e != i0 && acc[e] > acc[i1]) i1 = e;
        float w0 = 1.f / (1.f + __expf(acc[i1] - acc[i0]));
        g_pair_expert[2 * token] = i0;     g_pair_w[2 * token] = w0;
        g_pair_expert[2 * token + 1] = i1; g_pair_w[2 * token + 1] = 1.f - w0;
        atomicAdd(&g_counts[i0], 1);
        atomicAdd(&g_counts[i1], 1);
    }
}

__global__ void scan_kernel() {
    if (threadIdx.x != 0 || blockIdx.x != 0) return;
    int off = 0;
    for (int e = 0; e < NE; e++) { g_offsets[e] = off; g_cursor[e] = off; off += g_counts[e]; }
    g_offsets[NE] = off;
    int nt = 0;
    for (int e = 0; e < NE; e++) {
        int base = g_offsets[e], m = g_counts[e];
        for (int mb = 0; mb < m; mb += BM) { g_tile_e[nt] = e; g_tile_row[nt] = base + mb; nt++; }
    }
    g_num_tiles = nt;
}

__global__ void scatter_kernel() {
    int p = blockIdx.x * blockDim.x + threadIdx.x;
    if (p >= NP) return;
    int e = g_pair_expert[p];
    int s = atomicAdd(&g_cursor[e], 1);
    g_bucket_pair[s] = p;
    g_row_of_pair[p] = s;
}

// fp32 W[sec][e][k][n] -> bf16 hi [k][n]  +  fp8 hi/lo transposed [n][k]
__global__ void wsplit_kernel(const float* __restrict__ wg,
                              const float* __restrict__ wu,
                              const float* __restrict__ wd) {
    __shared__ float tile[32][33];
    int b = blockIdx.x;
    int nt = b & 31; b >>= 5;
    int kt = b & 31; b >>= 5;
    int e  = b & 7;  b >>= 3;
    int sec = b;
    const float* src = (sec == 0) ? wg : (sec == 1) ? wu : wd;
    src += (size_t)e * DD * DD;
    size_t base = ((size_t)sec * NE + e) * DD * DD;

    int tx = threadIdx.x & 31, ty = threadIdx.x >> 5;   // 32 x 8
    #pragma unroll
    for (int i = 0; i < 4; i++) {
        int k = kt * 32 + ty + i * 8, n = nt * 32 + tx;
        float v = src[(size_t)k * DD + n];
        tile[ty + i * 8][tx] = v;
        g_Whi[base + (size_t)k * DD + n] = __float2bfloat16_rn(v);
    }
    __syncthreads();
    #pragma unroll
    for (int i = 0; i < 4; i++) {
        int n = nt * 32 + ty + i * 8, k = kt * 32 + tx;
        float v = tile[tx][ty + i * 8];
        __nv_bfloat16 h = __float2bfloat16_rn(v);
        float hf = __bfloat162float(h);
        g_W8h[base + (size_t)n * DD + k] = f2e4m3(hf);
        g_W8l[base + (size_t)n * DD + k] = f2e4m3((v - hf) * 256.f);
    }
}

__global__ void xgather_kernel(const float* __restrict__ x) {
    size_t idx = (size_t)blockIdx.x * blockDim.x + threadIdx.x;
    int s = (int)(idx >> 8);
    int d = (int)(idx & 255) * 4;
    int t = g_bucket_pair[s] >> 1;
    float4 v = *(const float4*)(x + (size_t)t * DD + d);
    size_t base = (size_t)s * DD + d;
    __nv_bfloat16 h0 = __float2bfloat16_rn(v.x), h1 = __float2bfloat16_rn(v.y);
    __nv_bfloat16 h2 = __float2bfloat16_rn(v.z), h3 = __float2bfloat16_rn(v.w);
    *(__nv_bfloat162*)(g_Xh + base)     = __nv_bfloat162(h0, h1);
    *(__nv_bfloat162*)(g_Xh + base + 2) = __nv_bfloat162(h2, h3);
    float f0 = __bfloat162float(h0), f1 = __bfloat162float(h1);
    float f2 = __bfloat162float(h2), f3 = __bfloat162float(h3);
    uint32_t ph = (uint32_t)f2e4m3(f0) | ((uint32_t)f2e4m3(f1) << 8)
                | ((uint32_t)f2e4m3(f2) << 16) | ((uint32_t)f2e4m3(f3) << 24);
    uint32_t pl = (uint32_t)f2e4m3((v.x - f0) * 256.f) | ((uint32_t)f2e4m3((v.y - f1) * 256.f) << 8)
                | ((uint32_t)f2e4m3((v.z - f2) * 256.f) << 16) | ((uint32_t)f2e4m3((v.w - f3) * 256.f) << 24);
    *(uint32_t*)(g_X8h + base) = ph;
    *(uint32_t*)(g_X8l + base) = pl;
}

__global__ void act_kernel() {
    size_t idx = (size_t)blockIdx.x * blockDim.x + threadIdx.x;
    size_t base = idx * 4;
    float4 g = *(const float4*)(g_t1 + base);
    float4 u = *(const float4*)(g_t2 + base);
    float4 a;
    a.x = u.x * g.x / (1.f + __expf(-g.x));
    a.y = u.y * g.y / (1.f + __expf(-g.y));
    a.z = u.z * g.z / (1.f + __expf(-g.z));
    a.w = u.w * g.w / (1.f + __expf(-g.w));
    __nv_bfloat16 h0 = __float2bfloat16_rn(a.x), h1 = __float2bfloat16_rn(a.y);
    __nv_bfloat16 h2 = __float2bfloat16_rn(a.z), h3 = __float2bfloat16_rn(a.w);
    *(__nv_bfloat162*)(g_A2h + base)     = __nv_bfloat162(h0, h1);
    *(__nv_bfloat162*)(g_A2h + base + 2) = __nv_bfloat162(h2, h3);
    float f0 = __bfloat162float(h0), f1 = __bfloat162float(h1);
    float f2 = __bfloat162float(h2), f3 = __bfloat162float(h3);
    uint32_t ph = (uint32_t)f2e4m3(f0) | ((uint32_t)f2e4m3(f1) << 8)
                | ((uint32_t)f2e4m3(f2) << 16) | ((uint32_t)f2e4m3(f3) << 24);
    uint32_t pl = (uint32_t)f2e4m3((a.x - f0) * 256.f) | ((uint32_t)f2e4m3((a.y - f1) * 256.f) << 8)
                | ((uint32_t)f2e4m3((a.z - f2) * 256.f) << 16) | ((uint32_t)f2e4m3((a.w - f3) * 256.f) << 24);
    *(uint32_t*)(g_A28h + base) = ph;
    *(uint32_t*)(g_A28l + base) = pl;
}

__global__ void combine_kernel(float* __restrict__ out) {
    size_t idx = (size_t)blockIdx.x * blockDim.x + threadIdx.x;
    int t = (int)(idx >> 8);
    int d = (int)(idx & 255) * 4;
    int r0 = g_row_of_pair[2 * t];
    int r1 = g_row_of_pair[2 * t + 1];
    float w0 = g_pair_w[2 * t];
    float w1 = g_pair_w[2 * t + 1];
    float4 y0 = *(const float4*)(g_t1 + (size_t)r0 * DD + d);
    float4 y1 = *(const float4*)(g_t1 + (size_t)r1 * DD + d);
    float4 o;
    o.x = w0 * y0.x + w1 * y1.x;
    o.y = w0 * y0.y + w1 * y1.y;
    o.z = w0 * y0.z + w1 * y1.z;
    o.w = w0 * y0.w + w1 * y1.w;
    *(float4*)(out + (size_t)t * DD + d) = o;
}

// ---------------- grouped GEMM: bf16 hh + fp8 correction --------------------
__global__ void __launch_bounds__(256, 1)
gemm_kernel(const __nv_bfloat16* __restrict__ Ah,
            const uint8_t* __restrict__ A8h,
            const uint8_t* __restrict__ A8l,
            const __nv_bfloat16* __restrict__ Wh,    // section base, [e][k][n]
            const uint8_t* __restrict__ W8h,         // section base, [e][n][k]
            const uint8_t* __restrict__ W8l,
            float* __restrict__ Cout) {
    int tile = blockIdx.y;
    if (tile >= g_num_tiles) return;
    int e = g_tile_e[tile];
    int row0 = g_tile_row[tile];
    int row_end = g_offsets[e + 1];
    int n0 = blockIdx.x * BN;
    const __nv_bfloat16* Bh = Wh + (size_t)e * DD * DD;
    const uint8_t* B8h = W8h + (size_t)e * DD * DD;
    const uint8_t* B8l = W8l + (size_t)e * DD * DD;

    extern __shared__ char smem[];
    uint32_t sb = smem_u32(smem);

    int tid = threadIdx.x;
    int warp = tid >> 5, lane = tid & 31;
    int wm = warp >> 2, wn = warp & 3;           // 2x4 warps over 128x128
    int r16 = lane & 15, c8 = lane >> 4;
    int l8r = lane & 7, l8s = (lane >> 3) & 1;

    float C1[4][4][4], C2[4][4][4];
    #pragma unroll
    for (int mf = 0; mf < 4; mf++)
        #pragma unroll
        for (int nf = 0; nf < 4; nf++)
            #pragma unroll
            for (int i = 0; i < 4; i++) { C1[mf][nf][i] = 0.f; C2[mf][nf][i] = 0.f; }

    auto issue = [&](int kt, int buf) {
        int kb = kt * BK;
        uint32_t st = sb + buf * STAGE;
        #pragma unroll
        for (int i = 0; i < 2; i++) {            // A bf16: 512 vec
            int v = tid + i * 256;
            int r = v >> 2, kv = (v & 3) * 8;
            int gr = row0 + r;
            bool ok = gr < row_end;
            int grc = ok ? gr : row0;
            cp16(st + OFF_AH + (uint32_t)((r * SAK + kv) * 2),
                 Ah + (size_t)grc * DD + kb + kv, ok);
        }
        #pragma unroll
        for (int i = 0; i < 2; i++) {            // B bf16: 512 vec
            int v = tid + i * 256;
            int kr = v >> 4, nv = (v & 15) * 8;
            cp16(st + OFF_BH + (uint32_t)((kr * SBN + nv) * 2),
                 Bh + (size_t)(kb + kr) * DD + n0 + nv, true);
        }
        {                                        // A fp8 hi/lo: 256 vec each
            int r = tid >> 1, kv = (tid & 1) * 16;
            int gr = row0 + r;
            bool ok = gr < row_end;
            int grc = ok ? gr : row0;
            size_t go = (size_t)grc * DD + kb + kv;
            cp16(st + OFF_A8H + (uint32_t)(r * S8 + kv), A8h + go, ok);
            cp16(st + OFF_A8L + (uint32_t)(r * S8 + kv), A8l + go, ok);
        }
        {                                        // B fp8 hi/lo: 256 vec each
            int n = tid >> 1, kv = (tid & 1) * 16;
            size_t go = (size_t)(n0 + n) * DD + kb + kv;
            cp16(st + OFF_B8H + (uint32_t)(n * S8 + kv), B8h + go, true);
            cp16(st + OFF_B8L + (uint32_t)(n * S8 + kv), B8l + go, true);
        }
        asm volatile("cp.async.commit_group;\n");
    };

    auto compute = [&](int buf) {
        uint32_t st = sb + buf * STAGE;
        // bf16 hi*hi
        #pragma unroll
        for (int kk = 0; kk < 2; kk++) {
            uint32_t ah[4][4], bh[4][2];
            #pragma unroll
            for (int mf = 0; mf < 4; mf++)
                ldsm4(ah[mf], st + OFF_AH +
                      (uint32_t)(((wm * 64 + mf * 16 + r16) * SAK + kk * 16 + c8 * 8) * 2));
            #pragma unroll
            for (int nf = 0; nf < 4; nf++)
                ldsm2t(bh[nf], st + OFF_BH +
                       (uint32_t)(((kk * 16 + r16) * SBN + wn * 32 + nf * 8) * 2));
            #pragma unroll
            for (int mf = 0; mf < 4; mf++)
                #pragma unroll
                for (int nf = 0; nf < 4; nf++)
                    mma_bf16(C1[mf][nf], ah[mf], bh[nf]);
        }
        // fp8 corrections: Ah8*Bl8 + Al8*Bh8  (each k=32)
        uint32_t a8h[4][4], a8l[4][4], b8h[4][2], b8l[4][2];
        #pragma unroll
        for (int mf = 0; mf < 4; mf++) {
            uint32_t ad = st + OFF_A8H + (uint32_t)((wm * 64 + mf * 16 + r16) * S8 + c8 * 16);
            ldsm4(a8h[mf], ad);
            ldsm4(a8l[mf], ad + (OFF_A8L - OFF_A8H));
        }
        #pragma unroll
        for (int nf = 0; nf < 4; nf++) {
            uint32_t bd = st + OFF_B8H + (uint32_t)((wn * 32 + nf * 8 + l8r) * S8 + l8s * 16);
            ldsm2(b8h[nf], bd);
            ldsm2(b8l[nf], bd + (OFF_B8L - OFF_B8H));
        }
        #pragma unroll
        for (int mf = 0; mf < 4; mf++)
            #pragma unroll
            for (int nf = 0; nf < 4; nf++)
                mma_fp8(C2[mf][nf], a8h[mf], b8l[nf]);
        #pragma unroll
        for (int mf = 0; mf < 4; mf++)
            #pragma unroll
            for (int nf = 0; nf < 4; nf++)
                mma_fp8(C2[mf][nf], a8l[mf], b8h[nf]);
    };

    issue(0, 0);
    issue(1, 1);
    #pragma unroll 1
    for (int kt = 0; kt < KT; kt++) {
        if (kt < KT - 2) asm volatile("cp.async.wait_group 1;\n");
        else             asm volatile("cp.async.wait_group 0;\n");
        __syncthreads();
        if (kt + 2 < KT) issue(kt + 2, (kt + 2) % NSTAGE);
        compute(kt % NSTAGE);
    }

    // epilogue: merge and store fp32
    constexpr float INV = 1.f / 256.f;
    #pragma unroll
    for (int mf = 0; mf < 4; mf++) {
        int r = row0 + wm * 64 + mf * 16 + (lane >> 2);
        #pragma unroll
        for (int nf = 0; nf < 4; nf++) {
            int c = n0 + wn * 32 + nf * 8 + (lane & 3) * 2;
            float* p = Cout + (size_t)r * DD + c;
            float2 v0 = { C1[mf][nf][0] + C2[mf][nf][0] * INV,
                          C1[mf][nf][1] + C2[mf][nf][1] * INV };
            float2 v1 = { C1[mf][nf][2] + C2[mf][nf][2] * INV,
                          C1[mf][nf][3] + C2[mf][nf][3] * INV };
            if (r < row_end)     *(float2*)p = v0;
            if (r + 8 < row_end) *(float2*)(p + 8 * DD) = v1;
        }
    }
}

// ------------------------------ launcher ------------------------------------
extern "C" void kernel_launch(void* const* d_in, const int* in_sizes, int n_in,
                              void* d_out, int out_size) {
    const float* x  = (const float*)d_in[0];
    const float* rw = (const float*)d_in[1];
    const float* rb = (const float*)d_in[2];
    const float* wg = (const float*)d_in[3];
    const float* wu = (const float*)d_in[4];
    const float* wd = (const float*)d_in[5];
    float* out = (float*)d_out;

    cudaFuncSetAttribute(gemm_kernel, cudaFuncAttributeMaxDynamicSharedMemorySize, SMEM_BYTES);

    __nv_bfloat16 *whi_p, *xh_p, *a2h_p;
    uint8_t *w8h_p, *w8l_p, *x8h_p, *x8l_p, *a28h_p, *a28l_p;
    float *t1_p, *t2_p;
    cudaGetSymbolAddress((void**)&whi_p, g_Whi);
    cudaGetSymbolAddress((void**)&w8h_p, g_W8h);
    cudaGetSymbolAddress((void**)&w8l_p, g_W8l);
    cudaGetSymbolAddress((void**)&xh_p,  g_Xh);
    cudaGetSymbolAddress((void**)&x8h_p, g_X8h);
    cudaGetSymbolAddress((void**)&x8l_p, g_X8l);
    cudaGetSymbolAddress((void**)&a2h_p, g_A2h);
    cudaGetSymbolAddress((void**)&a28h_p, g_A28h);
    cudaGetSymbolAddress((void**)&a28l_p, g_A28l);
    cudaGetSymbolAddress((void**)&t1_p, g_t1);
    cudaGetSymbolAddress((void**)&t2_p, g_t2);

    const size_t WSEC = (size_t)NE * DD * DD;   // elements per section

    init_kernel<<<1, 32>>>();
    router_kernel<<<TT / 8, 256>>>(x, rw, rb);
    scan_kernel<<<1, 1>>>();
    scatter_kernel<<<NP / 256, 256>>>();

    wsplit_kernel<<<3 * NE * 32 * 32, 256>>>(wg, wu, wd);
    xgather_kernel<<<(unsigned)((size_t)NP * DD / 4 / 256), 256>>>(x);

    dim3 ggrid(DD / BN, MAXT);
    gemm_kernel<<<ggrid, 256, SMEM_BYTES>>>(xh_p, x8h_p, x8l_p,
                                            whi_p + 0 * WSEC, w8h_p + 0 * WSEC, w8l_p + 0 * WSEC, t1_p);
    gemm_kernel<<<ggrid, 256, SMEM_BYTES>>>(xh_p, x8h_p, x8l_p,
                                            whi_p + 1 * WSEC, w8h_p + 1 * WSEC, w8l_p + 1 * WSEC, t2_p);

    act_kernel<<<(unsigned)((size_t)NP * DD / 4 / 256), 256>>>();

    gemm_kernel<<<ggrid, 256, SMEM_BYTES>>>(a2h_p, a28h_p, a28l_p,
                                            whi_p + 2 * WSEC, w8h_p + 2 * WSEC, w8l_p + 2 * WSEC, t1_p);

    combine_kernel<<<(unsigned)((size_t)TT * DD / 4 / 256), 256>>>(out);
}

// round 4
// speedup vs baseline: 1.3831x; 1.3831x over previous
#include <cuda_runtime.h>
#include <cuda_bf16.h>
#include <cstdint>

// ---------------------------------------------------------------------------
// MoE layer (T=16384, D=1024, E=8, top-2). bf16x3 mma.sync grouped GEMMs.
// R4: GEMM = 128-thread CTAs (BM=64), 3-stage cp.async, 1 sync/iter, occ 2.
// ---------------------------------------------------------------------------

namespace {
constexpr int TT = 16384;
constexpr int DD = 1024;
constexpr int NE = 8;
constexpr int NP = TT * 2;          // 32768
constexpr int MAXT = 520;           // 32768/64 + 8 slack

constexpr int BM = 64, BN = 128, BK = 32;
constexpr int KT = DD / BK;         // 32
constexpr int NSTAGE = 3;

constexpr int SAK = 40;             // A smem row stride (bf16 elems)
constexpr int SBN = 136;            // B smem row stride (bf16 elems)
constexpr int OFF_AH = 0;                       // 64*40*2  = 5120
constexpr int OFF_AL = 5120;
constexpr int OFF_BH = 10240;                   // 32*136*2 = 8704
constexpr int OFF_BL = 18944;
constexpr int STAGE  = 27648;
constexpr int SMEM_BYTES = NSTAGE * STAGE;      // 82944
} // namespace

// ------------------------- device scratch (static) -------------------------
__device__ int g_counts[NE];
__device__ int g_offsets[NE + 1];
__device__ int g_cursor[NE];
__device__ int g_pair_expert[NP];
__device__ float g_pair_w[NP];
__device__ int g_bucket_pair[NP];
__device__ int g_row_of_pair[NP];
__device__ int g_tile_e[MAXT];
__device__ int g_tile_row[MAXT];
__device__ int g_num_tiles;

__device__ __nv_bfloat16 g_Whi[3ull * NE * DD * DD];  // [sec][e][k][n]
__device__ __nv_bfloat16 g_Wlo[3ull * NE * DD * DD];
__device__ __nv_bfloat16 g_Xhi[(size_t)NP * DD];
__device__ __nv_bfloat16 g_Xlo[(size_t)NP * DD];
__device__ float g_t1[(size_t)NP * DD];
__device__ float g_t2[(size_t)NP * DD];
__device__ __nv_bfloat16 g_A2hi[(size_t)NP * DD];
__device__ __nv_bfloat16 g_A2lo[(size_t)NP * DD];

// ------------------------------- helpers -----------------------------------
__device__ __forceinline__ uint32_t smem_u32(const void* p) {
    return (uint32_t)__cvta_generic_to_shared(p);
}
__device__ __forceinline__ void cp16(uint32_t s, const void* g, bool pred) {
    int sz = pred ? 16 : 0;
    asm volatile("cp.async.cg.shared.global [%0], [%1], 16, %2;\n"
                 :: "r"(s), "l"(g), "r"(sz));
}
__device__ __forceinline__ void ldsm4(uint32_t* r, uint32_t addr) {
    asm volatile("ldmatrix.sync.aligned.m8n8.x4.shared.b16 {%0,%1,%2,%3}, [%4];"
                 : "=r"(r[0]), "=r"(r[1]), "=r"(r[2]), "=r"(r[3]) : "r"(addr));
}
__device__ __forceinline__ void ldsm2t(uint32_t* r, uint32_t addr) {
    asm volatile("ldmatrix.sync.aligned.m8n8.x2.trans.shared.b16 {%0,%1}, [%2];"
                 : "=r"(r[0]), "=r"(r[1]) : "r"(addr));
}
__device__ __forceinline__ void mma_bf16(float* c, const uint32_t* a, const uint32_t* b) {
    asm volatile(
        "mma.sync.aligned.m16n8k16.row.col.f32.bf16.bf16.f32 "
        "{%0,%1,%2,%3}, {%4,%5,%6,%7}, {%8,%9}, {%0,%1,%2,%3};\n"
        : "+f"(c[0]), "+f"(c[1]), "+f"(c[2]), "+f"(c[3])
        : "r"(a[0]), "r"(a[1]), "r"(a[2]), "r"(a[3]), "r"(b[0]), "r"(b[1]));
}
__device__ __forceinline__ void split2(float v, __nv_bfloat16& h, __nv_bfloat16& l) {
    h = __float2bfloat16_rn(v);
    l = __float2bfloat16_rn(v - __bfloat162float(h));
}

// ------------------------------- small kernels ------------------------------
__global__ void init_kernel() {
    int i = threadIdx.x;
    if (i < NE) g_counts[i] = 0;
}

__global__ void router_kernel(const float* __restrict__ x,
                              const float* __restrict__ rw,
                              const float* __restrict__ rb) {
    int warp = threadIdx.x >> 5;
    int lane = threadIdx.x & 31;
    int token = blockIdx.x * (blockDim.x >> 5) + warp;
    if (token >= TT) return;

    const float4* xr = (const float4*)(x + (size_t)token * DD);
    float acc[NE];
    #pragma unroll
    for (int e = 0; e < NE; e++) acc[e] = 0.f;
    for (int i = lane; i < DD / 4; i += 32) {
        float4 v = xr[i];
        const float* r0 = rw + i * 4 * NE;
        #pragma unroll
        for (int e = 0; e < NE; e++)
            acc[e] += v.x * r0[e] + v.y * r0[NE + e] + v.z * r0[2 * NE + e] + v.w * r0[3 * NE + e];
    }
    #pragma unroll
    for (int off = 16; off; off >>= 1)
        #pragma unroll
        for (int e = 0; e < NE; e++)
            acc[e] += __shfl_xor_sync(0xFFFFFFFFu, acc[e], off);

    if (lane == 0) {
        #pragma unroll
        for (int e = 0; e < NE; e++) acc[e] += rb[e];
        int i0 = 0;
        #pragma unroll
        for (int e = 1; e < NE; e++) if (acc[e] > acc[i0]) i0 = e;
        int i1 = (i0 == 0) ? 1 : 0;
        #pragma unroll
        for (int e = 0; e < NE; e++) if (e != i0 && acc[e] > acc[i1]) i1 = e;
        float w0 = 1.f / (1.f + __expf(acc[i1] - acc[i0]));
        g_pair_expert[2 * token] = i0;     g_pair_w[2 * token] = w0;
        g_pair_expert[2 * token + 1] = i1; g_pair_w[2 * token + 1] = 1.f - w0;
        atomicAdd(&g_counts[i0], 1);
        atomicAdd(&g_counts[i1], 1);
    }
}

__global__ void scan_kernel() {
    if (threadIdx.x != 0 || blockIdx.x != 0) return;
    int off = 0;
    for (int e = 0; e < NE; e++) { g_offsets[e] = off; g_cursor[e] = off; off += g_counts[e]; }
    g_offsets[NE] = off;
    int nt = 0;
    for (int e = 0; e < NE; e++) {
        int base = g_offsets[e], m = g_counts[e];
        for (int mb = 0; mb < m; mb += BM) { g_tile_e[nt] = e; g_tile_row[nt] = base + mb; nt++; }
    }
    g_num_tiles = nt;
}

__global__ void scatter_kernel() {
    int p = blockIdx.x * blockDim.x + threadIdx.x;
    if (p >= NP) return;
    int e = g_pair_expert[p];
    int s = atomicAdd(&g_cursor[e], 1);
    g_bucket_pair[s] = p;
    g_row_of_pair[p] = s;
}

__global__ void wsplit_kernel(const float* __restrict__ src,
                              __nv_bfloat16* __restrict__ dhi,
                              __nv_bfloat16* __restrict__ dlo) {
    size_t idx = (size_t)blockIdx.x * blockDim.x + threadIdx.x;
    size_t base = idx * 4;
    float4 v = *(const float4*)(src + base);
    __nv_bfloat16 h0, h1, h2, h3, l0, l1, l2, l3;
    split2(v.x, h0, l0); split2(v.y, h1, l1); split2(v.z, h2, l2); split2(v.w, h3, l3);
    __nv_bfloat162* ph = (__nv_bfloat162*)(dhi + base);
    __nv_bfloat162* pl = (__nv_bfloat162*)(dlo + base);
    ph[0] = __nv_bfloat162(h0, h1); ph[1] = __nv_bfloat162(h2, h3);
    pl[0] = __nv_bfloat162(l0, l1); pl[1] = __nv_bfloat162(l2, l3);
}

__global__ void xgather_kernel(const float* __restrict__ x) {
    size_t idx = (size_t)blockIdx.x * blockDim.x + threadIdx.x;
    int s = (int)(idx >> 8);
    int d = (int)(idx & 255) * 4;
    int t = g_bucket_pair[s] >> 1;
    float4 v = *(const float4*)(x + (size_t)t * DD + d);
    __nv_bfloat16 h0, h1, h2, h3, l0, l1, l2, l3;
    split2(v.x, h0, l0); split2(v.y, h1, l1); split2(v.z, h2, l2); split2(v.w, h3, l3);
    size_t base = (size_t)s * DD + d;
    *(__nv_bfloat162*)(g_Xhi + base)     = __nv_bfloat162(h0, h1);
    *(__nv_bfloat162*)(g_Xhi + base + 2) = __nv_bfloat162(h2, h3);
    *(__nv_bfloat162*)(g_Xlo + base)     = __nv_bfloat162(l0, l1);
    *(__nv_bfloat162*)(g_Xlo + base + 2) = __nv_bfloat162(l2, l3);
}

__global__ void act_kernel() {
    size_t idx = (size_t)blockIdx.x * blockDim.x + threadIdx.x;
    size_t base = idx * 4;
    float4 g = *(const float4*)(g_t1 + base);
    float4 u = *(const float4*)(g_t2 + base);
    float4 a;
    a.x = u.x * g.x / (1.f + __expf(-g.x));
    a.y = u.y * g.y / (1.f + __expf(-g.y));
    a.z = u.z * g.z / (1.f + __expf(-g.z));
    a.w = u.w * g.w / (1.f + __expf(-g.w));
    __nv_bfloat16 h0, h1, h2, h3, l0, l1, l2, l3;
    split2(a.x, h0, l0); split2(a.y, h1, l1); split2(a.z, h2, l2); split2(a.w, h3, l3);
    *(__nv_bfloat162*)(g_A2hi + base)     = __nv_bfloat162(h0, h1);
    *(__nv_bfloat162*)(g_A2hi + base + 2) = __nv_bfloat162(h2, h3);
    *(__nv_bfloat162*)(g_A2lo + base)     = __nv_bfloat162(l0, l1);
    *(__nv_bfloat162*)(g_A2lo + base + 2) = __nv_bfloat162(l2, l3);
}

__global__ void combine_kernel(float* __restrict__ out) {
    size_t idx = (size_t)blockIdx.x * blockDim.x + threadIdx.x;
    int t = (int)(idx >> 8);
    int d = (int)(idx & 255) * 4;
    int r0 = g_row_of_pair[2 * t];
    int r1 = g_row_of_pair[2 * t + 1];
    float w0 = g_pair_w[2 * t];
    float w1 = g_pair_w[2 * t + 1];
    float4 y0 = *(const float4*)(g_t1 + (size_t)r0 * DD + d);
    float4 y1 = *(const float4*)(g_t1 + (size_t)r1 * DD + d);
    float4 o;
    o.x = w0 * y0.x + w1 * y1.x;
    o.y = w0 * y0.y + w1 * y1.y;
    o.z = w0 * y0.z + w1 * y1.z;
    o.w = w0 * y0.w + w1 * y1.w;
    *(float4*)(out + (size_t)t * DD + d) = o;
}

// ------------------- grouped GEMM (bf16x3, 128 thr, occ 2) ------------------
__global__ void __launch_bounds__(128, 2)
gemm_kernel(const __nv_bfloat16* __restrict__ Ahi,
            const __nv_bfloat16* __restrict__ Alo,
            const __nv_bfloat16* __restrict__ Wsec_hi,
            const __nv_bfloat16* __restrict__ Wsec_lo,
            float* __restrict__ Cout) {
    int tile = blockIdx.y;
    if (tile >= g_num_tiles) return;
    int e = g_tile_e[tile];
    int row0 = g_tile_row[tile];
    int row_end = g_offsets[e + 1];
    int n0 = blockIdx.x * BN;
    const __nv_bfloat16* Bhi = Wsec_hi + (size_t)e * DD * DD;
    const __nv_bfloat16* Blo = Wsec_lo + (size_t)e * DD * DD;

    extern __shared__ char smem[];
    uint32_t sb = smem_u32(smem);

    int tid = threadIdx.x;
    int wn = tid >> 5, lane = tid & 31;      // 4 warps: warp n-slice = wn*32
    int r16 = lane & 15, c8 = lane >> 4;

    float C[4][4][4];
    #pragma unroll
    for (int mf = 0; mf < 4; mf++)
        #pragma unroll
        for (int nf = 0; nf < 4; nf++)
            #pragma unroll
            for (int i = 0; i < 4; i++) C[mf][nf][i] = 0.f;

    auto issue = [&](int kt, int buf) {
        int kb = kt * BK;
        uint32_t st = sb + buf * STAGE;
        #pragma unroll
        for (int i = 0; i < 2; i++) {           // A hi+lo: 256 vec each
            int v = tid + i * 128;
            int r = v >> 2, kv = (v & 3) * 8;
            int gr = row0 + r;
            bool ok = gr < row_end;
            int grc = ok ? gr : row0;
            size_t go = (size_t)grc * DD + kb + kv;
            uint32_t so = (uint32_t)((r * SAK + kv) * 2);
            cp16(st + OFF_AH + so, Ahi + go, ok);
            cp16(st + OFF_AL + so, Alo + go, ok);
        }
        #pragma unroll
        for (int i = 0; i < 4; i++) {           // B hi+lo: 512 vec each
            int v = tid + i * 128;
            int kr = v >> 4, nv = (v & 15) * 8;
            size_t go = (size_t)(kb + kr) * DD + n0 + nv;
            uint32_t so = (uint32_t)((kr * SBN + nv) * 2);
            cp16(st + OFF_BH + so, Bhi + go, true);
            cp16(st + OFF_BL + so, Blo + go, true);
        }
        asm volatile("cp.async.commit_group;\n");
    };

    auto compute = [&](int buf) {
        uint32_t st = sb + buf * STAGE;
        #pragma unroll
        for (int kk = 0; kk < 2; kk++) {
            uint32_t ah[4][4], al[4][4], bh[4][2], bl[4][2];
            #pragma unroll
            for (int mf = 0; mf < 4; mf++) {
                uint32_t off = (uint32_t)(((mf * 16 + r16) * SAK + kk * 16 + c8 * 8) * 2);
                ldsm4(ah[mf], st + OFF_AH + off);
                ldsm4(al[mf], st + OFF_AL + off);
            }
            #pragma unroll
            for (int nf = 0; nf < 4; nf++) {
                uint32_t off = (uint32_t)(((kk * 16 + r16) * SBN + wn * 32 + nf * 8) * 2);
                ldsm2t(bh[nf], st + OFF_BH + off);
                ldsm2t(bl[nf], st + OFF_BL + off);
            }
            #pragma unroll
            for (int mf = 0; mf < 4; mf++)
                #pragma unroll
                for (int nf = 0; nf < 4; nf++) {
                    mma_bf16(C[mf][nf], ah[mf], bh[nf]);
                    mma_bf16(C[mf][nf], ah[mf], bl[nf]);
                    mma_bf16(C[mf][nf], al[mf], bh[nf]);
                }
        }
    };

    issue(0, 0);
    issue(1, 1);
    #pragma unroll 1
    for (int kt = 0; kt < KT; kt++) {
        if (kt < KT - 2) asm volatile("cp.async.wait_group 1;\n");
        else             asm volatile("cp.async.wait_group 0;\n");
        __syncthreads();
        if (kt + 2 < KT) issue(kt + 2, (kt + 2) % NSTAGE);
        compute(kt % NSTAGE);
    }

    #pragma unroll
    for (int mf = 0; mf < 4; mf++) {
        int r = row0 + mf * 16 + (lane >> 2);
        #pragma unroll
        for (int nf = 0; nf < 4; nf++) {
            int c = n0 + wn * 32 + nf * 8 + (lane & 3) * 2;
            float* p = Cout + (size_t)r * DD + c;
            if (r < row_end)     { p[0] = C[mf][nf][0]; p[1] = C[mf][nf][1]; }
            if (r + 8 < row_end) { p[8 * DD] = C[mf][nf][2]; p[8 * DD + 1] = C[mf][nf][3]; }
        }
    }
}

// ------------------------------ launcher ------------------------------------
extern "C" void kernel_launch(void* const* d_in, const int* in_sizes, int n_in,
                              void* d_out, int out_size) {
    const float* x  = (const float*)d_in[0];
    const float* rw = (const float*)d_in[1];
    const float* rb = (const float*)d_in[2];
    const float* wg = (const float*)d_in[3];
    const float* wu = (const float*)d_in[4];
    const float* wd = (const float*)d_in[5];
    float* out = (float*)d_out;

    cudaFuncSetAttribute(gemm_kernel, cudaFuncAttributeMaxDynamicSharedMemorySize, SMEM_BYTES);

    __nv_bfloat16 *whi_p, *wlo_p, *xhi_p, *xlo_p, *a2hi_p, *a2lo_p;
    float *t1_p, *t2_p;
    cudaGetSymbolAddress((void**)&whi_p, g_Whi);
    cudaGetSymbolAddress((void**)&wlo_p, g_Wlo);
    cudaGetSymbolAddress((void**)&xhi_p, g_Xhi);
    cudaGetSymbolAddress((void**)&xlo_p, g_Xlo);
    cudaGetSymbolAddress((void**)&a2hi_p, g_A2hi);
    cudaGetSymbolAddress((void**)&a2lo_p, g_A2lo);
    cudaGetSymbolAddress((void**)&t1_p, g_t1);
    cudaGetSymbolAddress((void**)&t2_p, g_t2);

    const size_t WSEC = (size_t)NE * DD * DD;

    init_kernel<<<1, 32>>>();
    router_kernel<<<TT / 8, 256>>>(x, rw, rb);
    scan_kernel<<<1, 1>>>();
    scatter_kernel<<<NP / 256, 256>>>();

    wsplit_kernel<<<(unsigned)(WSEC / 4 / 256), 256>>>(wg, whi_p + 0 * WSEC, wlo_p + 0 * WSEC);
    wsplit_kernel<<<(unsigned)(WSEC / 4 / 256), 256>>>(wu, whi_p + 1 * WSEC, wlo_p + 1 * WSEC);
    wsplit_kernel<<<(unsigned)(WSEC / 4 / 256), 256>>>(wd, whi_p + 2 * WSEC, wlo_p + 2 * WSEC);

    xgather_kernel<<<(unsigned)((size_t)NP * DD / 4 / 256), 256>>>(x);

    dim3 ggrid(DD / BN, MAXT);
    gemm_kernel<<<ggrid, 128, SMEM_BYTES>>>(xhi_p, xlo_p, whi_p + 0 * WSEC, wlo_p + 0 * WSEC, t1_p);
    gemm_kernel<<<ggrid, 128, SMEM_BYTES>>>(xhi_p, xlo_p, whi_p + 1 * WSEC, wlo_p + 1 * WSEC, t2_p);

    act_kernel<<<(unsigned)((size_t)NP * DD / 4 / 256), 256>>>();

    gemm_kernel<<<ggrid, 128, SMEM_BYTES>>>(a2hi_p, a2lo_p, whi_p + 2 * WSEC, wlo_p + 2 * WSEC, t1_p);

    combine_kernel<<<(unsigned)((size_t)TT * DD / 4 / 256), 256>>>(out);
}